// round 7
// baseline (speedup 1.0000x reference)
#include <cuda_runtime.h>
#include <math.h>

#define H 2048
#define V 50257
#define L 20

// Scratch (device globals: no allocation allowed in kernel_launch)
__device__ __align__(16) float g_concat[2 * H];   // [embedded ; context]
__device__ __align__(16) float g_x[H];            // relu(comb) output
__device__ __align__(16) float g_gh[3 * H];       // w_hh @ h0 + b_hh
__device__ __align__(16) float g_hnew[H];         // new hidden

__device__ __forceinline__ float warp_reduce(float v) {
    #pragma unroll
    for (int o = 16; o > 0; o >>= 1)
        v += __shfl_xor_sync(0xFFFFFFFFu, v, o);
    return v;
}

// ---------------------------------------------------------------------------
// K1: embedding gather + attention scores + softmax + context + concat vector
// One CTA, 1024 threads (32 warps).
// ---------------------------------------------------------------------------
__global__ void k1_attn(const int* __restrict__ input_ids,
                        const float* __restrict__ hidden,     // [H]
                        const float* __restrict__ enc,        // [L, H]
                        const float* __restrict__ emb,        // [V, H]
                        const float* __restrict__ attn_w,     // [L, 2H]
                        const float* __restrict__ attn_b,     // [L]
                        float* __restrict__ out)              // attn_weights -> out[V+H ..]
{
    __shared__ float s_sc[L];
    __shared__ float s_w[L];

    const int tid  = threadIdx.x;
    const int warp = tid >> 5;
    const int lane = tid & 31;
    const int id   = input_ids[0];
    const float4* emb4 = reinterpret_cast<const float4*>(emb + (long long)id * H);
    const float4* h4   = reinterpret_cast<const float4*>(hidden);

    // Phase A: warps 0..19 compute one attention score each.
    if (warp < L) {
        const float4* aw4 = reinterpret_cast<const float4*>(attn_w + warp * (2 * H));
        float sum = 0.f;
        // 2H = 4096 floats = 1024 float4; 32 per lane
        #pragma unroll 8
        for (int i = lane; i < 1024; i += 32) {
            float4 a = aw4[i];
            float4 x = (i < 512) ? emb4[i] : h4[i - 512];
            sum += a.x * x.x + a.y * x.y + a.z * x.z + a.w * x.w;
        }
        sum = warp_reduce(sum);
        if (lane == 0) s_sc[warp] = sum + attn_b[warp];
    }
    __syncthreads();

    // Phase B: softmax over 20 (thread 0, trivial)
    if (tid == 0) {
        float m = s_sc[0];
        #pragma unroll
        for (int l = 1; l < L; l++) m = fmaxf(m, s_sc[l]);
        float s = 0.f;
        #pragma unroll
        for (int l = 0; l < L; l++) { s_w[l] = __expf(s_sc[l] - m); s += s_w[l]; }
        float inv = 1.f / s;
        #pragma unroll
        for (int l = 0; l < L; l++) {
            s_w[l] *= inv;
            out[V + H + l] = s_w[l];
        }
    }
    __syncthreads();

    // Phase C: context + concat vector. 2048 j's over 1024 threads.
    const float* emb_row = emb + (long long)id * H;
    #pragma unroll
    for (int rep = 0; rep < 2; rep++) {
        int j = tid + rep * 1024;
        float ctx = 0.f;
        #pragma unroll
        for (int l = 0; l < L; l++)
            ctx += s_w[l] * enc[l * H + j];
        g_concat[j]     = emb_row[j];
        g_concat[H + j] = ctx;
    }
}

// ---------------------------------------------------------------------------
// K2: fused comb GEMV (rows 0..2047, len 4096, relu) and gh GEMV
//     (rows 2048..8191 -> w_hh rows 0..6143, len 2048).
// 256 threads/CTA, one warp per row. grid = 1024.
// ---------------------------------------------------------------------------
__global__ void k2_comb_gh(const float* __restrict__ comb_w,  // [H, 2H]
                           const float* __restrict__ comb_b,  // [H]
                           const float* __restrict__ w_hh,    // [3H, H]
                           const float* __restrict__ b_hh,    // [3H]
                           const float* __restrict__ hidden)  // [H]
{
    const int warp = threadIdx.x >> 5;
    const int lane = threadIdx.x & 31;
    const int r    = blockIdx.x * 8 + warp;

    if (r < H) {
        const float4* w4 = reinterpret_cast<const float4*>(comb_w + (long long)r * (2 * H));
        const float4* x4 = reinterpret_cast<const float4*>(g_concat);
        float sum = 0.f;
        #pragma unroll 8
        for (int i = lane; i < 1024; i += 32) {
            float4 a = w4[i], b = x4[i];
            sum += a.x * b.x + a.y * b.y + a.z * b.z + a.w * b.w;
        }
        sum = warp_reduce(sum);
        if (lane == 0) g_x[r] = fmaxf(sum + comb_b[r], 0.f);
    } else {
        const int rr = r - H;                       // 0..6143
        const float4* w4 = reinterpret_cast<const float4*>(w_hh + (long long)rr * H);
        const float4* x4 = reinterpret_cast<const float4*>(hidden);
        float sum = 0.f;
        #pragma unroll 8
        for (int i = lane; i < 512; i += 32) {
            float4 a = w4[i], b = x4[i];
            sum += a.x * b.x + a.y * b.y + a.z * b.z + a.w * b.w;
        }
        sum = warp_reduce(sum);
        if (lane == 0) g_gh[rr] = sum + b_hh[rr];
    }
}

// ---------------------------------------------------------------------------
// K3: per output element k: 3 gi dots (w_ih rows k, k+H, k+2H vs g_x) then
// GRU gate math -> h_new. grid = 2048, block = 96 (3 warps).
// ---------------------------------------------------------------------------
__global__ void k3_gru(const float* __restrict__ w_ih,   // [3H, H]
                       const float* __restrict__ b_ih,   // [3H]
                       const float* __restrict__ hidden, // [H]
                       float* __restrict__ out)          // h_new -> out[V ..]
{
    __shared__ float s_gi[3];
    const int warp = threadIdx.x >> 5;
    const int lane = threadIdx.x & 31;
    const int k    = blockIdx.x;
    const int row  = k + warp * H;

    const float4* w4 = reinterpret_cast<const float4*>(w_ih + (long long)row * H);
    const float4* x4 = reinterpret_cast<const float4*>(g_x);
    float sum = 0.f;
    #pragma unroll 8
    for (int i = lane; i < 512; i += 32) {
        float4 a = w4[i], b = x4[i];
        sum += a.x * b.x + a.y * b.y + a.z * b.z + a.w * b.w;
    }
    sum = warp_reduce(sum);
    if (lane == 0) s_gi[warp] = sum + b_ih[row];
    __syncthreads();

    if (threadIdx.x == 0) {
        float i_r = s_gi[0], i_z = s_gi[1], i_n = s_gi[2];
        float h_r = g_gh[k], h_z = g_gh[k + H], h_n = g_gh[k + 2 * H];
        float rr = 1.f / (1.f + __expf(-(i_r + h_r)));
        float zz = 1.f / (1.f + __expf(-(i_z + h_z)));
        float nn = tanhf(i_n + rr * h_n);
        float h0 = hidden[k];
        float hn = (1.f - zz) * nn + zz * h0;
        g_hnew[k]  = hn;
        out[V + k] = hn;
    }
}

// ---------------------------------------------------------------------------
// K4: logits = out_w @ h_new + out_b. 50257 rows of 2048. One warp per row.
// 256 threads/CTA (8 warps), grid = ceil(V/8).
// ---------------------------------------------------------------------------
__global__ void k4_logits(const float* __restrict__ out_w,  // [V, H]
                          const float* __restrict__ out_b,  // [V]
                          float* __restrict__ out)          // logits -> out[0..V)
{
    const int warp = threadIdx.x >> 5;
    const int lane = threadIdx.x & 31;
    const int r    = blockIdx.x * 8 + warp;
    if (r >= V) return;

    const float4* w4 = reinterpret_cast<const float4*>(out_w + (long long)r * H);
    const float4* x4 = reinterpret_cast<const float4*>(g_hnew);
    float sum = 0.f;
    #pragma unroll 16
    for (int i = lane; i < 512; i += 32) {
        float4 a = w4[i], b = x4[i];
        sum += a.x * b.x + a.y * b.y + a.z * b.z + a.w * b.w;
    }
    sum = warp_reduce(sum);
    if (lane == 0) out[r] = sum + out_b[r];
}

// ---------------------------------------------------------------------------
extern "C" void kernel_launch(void* const* d_in, const int* in_sizes, int n_in,
                              void* d_out, int out_size)
{
    const int*   input_ids = (const int*)  d_in[0];
    const float* hidden    = (const float*)d_in[1];
    const float* enc       = (const float*)d_in[2];
    const float* emb       = (const float*)d_in[3];
    const float* attn_w    = (const float*)d_in[4];
    const float* attn_b    = (const float*)d_in[5];
    const float* comb_w    = (const float*)d_in[6];
    const float* comb_b    = (const float*)d_in[7];
    const float* w_ih      = (const float*)d_in[8];
    const float* w_hh      = (const float*)d_in[9];
    const float* b_ih      = (const float*)d_in[10];
    const float* b_hh      = (const float*)d_in[11];
    const float* out_w     = (const float*)d_in[12];
    const float* out_b     = (const float*)d_in[13];
    float* out = (float*)d_out;

    k1_attn<<<1, 1024>>>(input_ids, hidden, enc, emb, attn_w, attn_b, out);
    k2_comb_gh<<<(H + 3 * H) / 8, 256>>>(comb_w, comb_b, w_hh, b_hh, hidden);
    k3_gru<<<H, 96>>>(w_ih, b_ih, hidden, out);
    k4_logits<<<(V + 7) / 8, 256>>>(out_w, out_b, out);
}

// round 8
// speedup vs baseline: 1.0809x; 1.0809x over previous
#include <cuda_runtime.h>
#include <math.h>

#define H 2048
#define V 50257
#define L 20

// Scratch (device globals: no allocation allowed in kernel_launch)
__device__ __align__(16) float g_sc[L];           // raw attention scores
__device__ __align__(16) float g_concat[2 * H];   // [embedded ; context]
__device__ __align__(16) float g_x[H];            // relu(comb) output
__device__ __align__(16) float g_gh[3 * H];       // w_hh @ h0 + b_hh
__device__ __align__(16) float g_hnew[H];         // new hidden

__device__ __forceinline__ float warp_reduce(float v) {
    #pragma unroll
    for (int o = 16; o > 0; o >>= 1)
        v += __shfl_xor_sync(0xFFFFFFFFu, v, o);
    return v;
}

__device__ __forceinline__ float dot4(float4 a, float4 b) {
    return a.x * b.x + a.y * b.y + a.z * b.z + a.w * b.w;
}

// ---------------------------------------------------------------------------
// K1a: attention scores. One CTA per l (20 CTAs, 256 threads).
// score[l] = attn_w[l] . [emb_row ; h0] + attn_b[l]
// ---------------------------------------------------------------------------
__global__ void k1a_scores(const int* __restrict__ input_ids,
                           const float* __restrict__ hidden,
                           const float* __restrict__ emb,
                           const float* __restrict__ attn_w,
                           const float* __restrict__ attn_b)
{
    __shared__ float red[8];
    const int l   = blockIdx.x;
    const int tid = threadIdx.x;
    const int id  = input_ids[0];

    const float4* aw = reinterpret_cast<const float4*>(attn_w + l * (2 * H));
    const float4* e4 = reinterpret_cast<const float4*>(emb + (long long)id * H);
    const float4* h4 = reinterpret_cast<const float4*>(hidden);

    float s = 0.f;
    #pragma unroll
    for (int i = tid; i < 1024; i += 256) {
        float4 a = __ldcs(aw + i);
        float4 x = (i < 512) ? e4[i] : h4[i - 512];
        s += dot4(a, x);
    }
    s = warp_reduce(s);
    if ((tid & 31) == 0) red[tid >> 5] = s;
    __syncthreads();
    if (tid < 8) {
        float v = red[tid];
        #pragma unroll
        for (int o = 4; o > 0; o >>= 1) v += __shfl_xor_sync(0xFFu, v, o);
        if (tid == 0) g_sc[l] = v + attn_b[l];
    }
}

// ---------------------------------------------------------------------------
// K1b: softmax (redundant per CTA, 20 values) + context + concat vector.
// grid = 16, block = 128 (each thread owns one j of 2048).
// ---------------------------------------------------------------------------
__global__ void k1b_ctx(const int* __restrict__ input_ids,
                        const float* __restrict__ enc,
                        const float* __restrict__ emb,
                        float* __restrict__ out)
{
    __shared__ float sw[L];
    const int tid = threadIdx.x;

    if (tid == 0) {
        float m = g_sc[0];
        #pragma unroll
        for (int l = 1; l < L; l++) m = fmaxf(m, g_sc[l]);
        float s = 0.f;
        float e[L];
        #pragma unroll
        for (int l = 0; l < L; l++) { e[l] = __expf(g_sc[l] - m); s += e[l]; }
        float inv = 1.f / s;
        #pragma unroll
        for (int l = 0; l < L; l++) sw[l] = e[l] * inv;
    }
    __syncthreads();

    const int j = blockIdx.x * 128 + tid;
    float ctx = 0.f;
    #pragma unroll
    for (int l = 0; l < L; l++)
        ctx += sw[l] * enc[l * H + j];

    const int id = input_ids[0];
    g_concat[j]     = emb[(long long)id * H + j];
    g_concat[H + j] = ctx;

    if (blockIdx.x == 0 && tid < L) out[V + H + tid] = sw[tid];
}

// ---------------------------------------------------------------------------
// K2: fused comb GEMV (CTAs 0..255: rows of comb_w, len 4096, relu -> g_x)
//     and gh GEMV (CTAs 256..1023: rows of w_hh, len 2048 -> g_gh).
// x staged in shared; streaming loads for weights. One warp per row.
// ---------------------------------------------------------------------------
__global__ void __launch_bounds__(256) k2_comb_gh(
    const float* __restrict__ comb_w, const float* __restrict__ comb_b,
    const float* __restrict__ w_hh,   const float* __restrict__ b_hh,
    const float* __restrict__ hidden)
{
    __shared__ float4 xs[1024];
    const int tid  = threadIdx.x;
    const int warp = tid >> 5;
    const int lane = tid & 31;

    if (blockIdx.x < 256) {
        for (int i = tid; i < 1024; i += 256)
            xs[i] = reinterpret_cast<const float4*>(g_concat)[i];
        __syncthreads();

        const int r = blockIdx.x * 8 + warp;
        const float4* w = reinterpret_cast<const float4*>(comb_w + (long long)r * (2 * H));
        float s = 0.f;
        #pragma unroll 8
        for (int i = lane; i < 1024; i += 32)
            s += dot4(__ldcs(w + i), xs[i]);
        s = warp_reduce(s);
        if (lane == 0) g_x[r] = fmaxf(s + comb_b[r], 0.f);
    } else {
        for (int i = tid; i < 512; i += 256)
            xs[i] = reinterpret_cast<const float4*>(hidden)[i];
        __syncthreads();

        const int r = (blockIdx.x - 256) * 8 + warp;      // 0..6143
        const float4* w = reinterpret_cast<const float4*>(w_hh + (long long)r * H);
        float s = 0.f;
        #pragma unroll 8
        for (int i = lane; i < 512; i += 32)
            s += dot4(__ldcs(w + i), xs[i]);
        s = warp_reduce(s);
        if (lane == 0) g_gh[r] = s + b_hh[r];
    }
}

// ---------------------------------------------------------------------------
// K3: each warp owns one output element k: interleaved dots with w_ih rows
// k, k+H, k+2H (3x MLP), then GRU gate math -> h_new. grid=256, block=256.
// ---------------------------------------------------------------------------
__global__ void __launch_bounds__(256) k3_gru(
    const float* __restrict__ w_ih, const float* __restrict__ b_ih,
    const float* __restrict__ hidden, float* __restrict__ out)
{
    __shared__ float4 xs[512];
    const int tid  = threadIdx.x;
    const int warp = tid >> 5;
    const int lane = tid & 31;

    for (int i = tid; i < 512; i += 256)
        xs[i] = reinterpret_cast<const float4*>(g_x)[i];
    __syncthreads();

    const int k = blockIdx.x * 8 + warp;
    const float4* base = reinterpret_cast<const float4*>(w_ih);
    const float4* wr = base + (long long)k * 512;
    const float4* wz = base + (long long)(k + H) * 512;
    const float4* wn = base + (long long)(k + 2 * H) * 512;

    float sr = 0.f, sz = 0.f, sn = 0.f;
    #pragma unroll 4
    for (int i = lane; i < 512; i += 32) {
        float4 b = xs[i];
        sr += dot4(__ldcs(wr + i), b);
        sz += dot4(__ldcs(wz + i), b);
        sn += dot4(__ldcs(wn + i), b);
    }
    sr = warp_reduce(sr);
    sz = warp_reduce(sz);
    sn = warp_reduce(sn);

    if (lane == 0) {
        float i_r = sr + b_ih[k];
        float i_z = sz + b_ih[k + H];
        float i_n = sn + b_ih[k + 2 * H];
        float h_r = g_gh[k], h_z = g_gh[k + H], h_n = g_gh[k + 2 * H];
        float rr = 1.f / (1.f + __expf(-(i_r + h_r)));
        float zz = 1.f / (1.f + __expf(-(i_z + h_z)));
        float nn = tanhf(i_n + rr * h_n);
        float h0 = hidden[k];
        float hn = (1.f - zz) * nn + zz * h0;
        g_hnew[k]  = hn;
        out[V + k] = hn;
    }
}

// ---------------------------------------------------------------------------
// K4: logits = out_w @ h_new + out_b. x staged in shared, streaming weight
// loads, 2 rows per warp (2x MLP). grid = ceil(V/16), block = 256.
// ---------------------------------------------------------------------------
__global__ void __launch_bounds__(256) k4_logits(
    const float* __restrict__ out_w, const float* __restrict__ out_b,
    float* __restrict__ out)
{
    __shared__ float4 xs[512];
    const int tid  = threadIdx.x;
    const int warp = tid >> 5;
    const int lane = tid & 31;

    for (int i = tid; i < 512; i += 256)
        xs[i] = reinterpret_cast<const float4*>(g_hnew)[i];
    __syncthreads();

    const long long r0 = ((long long)blockIdx.x * 8 + warp) * 2;
    if (r0 >= V) return;
    const bool two = (r0 + 1 < V);

    const float4* w0 = reinterpret_cast<const float4*>(out_w) + r0 * 512;
    const float4* w1 = w0 + (two ? 512 : 0);

    float s0 = 0.f, s1 = 0.f;
    #pragma unroll 8
    for (int i = lane; i < 512; i += 32) {
        float4 b = xs[i];
        s0 += dot4(__ldcs(w0 + i), b);
        s1 += dot4(__ldcs(w1 + i), b);
    }
    s0 = warp_reduce(s0);
    s1 = warp_reduce(s1);
    if (lane == 0) {
        out[r0] = s0 + out_b[r0];
        if (two) out[r0 + 1] = s1 + out_b[r0 + 1];
    }
}

// ---------------------------------------------------------------------------
extern "C" void kernel_launch(void* const* d_in, const int* in_sizes, int n_in,
                              void* d_out, int out_size)
{
    const int*   input_ids = (const int*)  d_in[0];
    const float* hidden    = (const float*)d_in[1];
    const float* enc       = (const float*)d_in[2];
    const float* emb       = (const float*)d_in[3];
    const float* attn_w    = (const float*)d_in[4];
    const float* attn_b    = (const float*)d_in[5];
    const float* comb_w    = (const float*)d_in[6];
    const float* comb_b    = (const float*)d_in[7];
    const float* w_ih      = (const float*)d_in[8];
    const float* w_hh      = (const float*)d_in[9];
    const float* b_ih      = (const float*)d_in[10];
    const float* b_hh      = (const float*)d_in[11];
    const float* out_w     = (const float*)d_in[12];
    const float* out_b     = (const float*)d_in[13];
    float* out = (float*)d_out;

    k1a_scores<<<L, 256>>>(input_ids, hidden, emb, attn_w, attn_b);
    k1b_ctx<<<16, 128>>>(input_ids, enc, emb, out);
    k2_comb_gh<<<1024, 256>>>(comb_w, comb_b, w_hh, b_hh, hidden);
    k3_gru<<<H / 8, 256>>>(w_ih, b_ih, hidden, out);
    k4_logits<<<(V + 15) / 16, 256>>>(out_w, out_b, out);
}

// round 9
// speedup vs baseline: 1.1146x; 1.0312x over previous
#include <cuda_runtime.h>
#include <math.h>

#define H 2048
#define V 50257
#define L 20

// Scratch (device globals: no allocation allowed in kernel_launch)
__device__ __align__(16) float g_sc[L];           // raw attention scores
__device__ __align__(16) float g_concat[2 * H];   // [embedded ; context]
__device__ __align__(16) float g_x[H];            // relu(comb) output
__device__ __align__(16) float g_gh[3 * H];       // w_hh @ h0 + b_hh
__device__ __align__(16) float g_hnew[H];         // new hidden

__device__ __forceinline__ float warp_reduce(float v) {
    #pragma unroll
    for (int o = 16; o > 0; o >>= 1)
        v += __shfl_xor_sync(0xFFFFFFFFu, v, o);
    return v;
}

__device__ __forceinline__ float dot4(float4 a, float4 b) {
    return a.x * b.x + a.y * b.y + a.z * b.z + a.w * b.w;
}

// ---------------------------------------------------------------------------
// K1a: attention scores. One CTA per l (20 CTAs, 256 threads).
// ---------------------------------------------------------------------------
__global__ void k1a_scores(const int* __restrict__ input_ids,
                           const float* __restrict__ hidden,
                           const float* __restrict__ emb,
                           const float* __restrict__ attn_w,
                           const float* __restrict__ attn_b)
{
    __shared__ float red[8];
    const int l   = blockIdx.x;
    const int tid = threadIdx.x;
    const int id  = input_ids[0];

    const float4* aw = reinterpret_cast<const float4*>(attn_w + l * (2 * H));
    const float4* e4 = reinterpret_cast<const float4*>(emb + (long long)id * H);
    const float4* h4 = reinterpret_cast<const float4*>(hidden);

    float s = 0.f;
    #pragma unroll
    for (int i = tid; i < 1024; i += 256) {
        float4 a = __ldcs(aw + i);
        float4 x = (i < 512) ? e4[i] : h4[i - 512];
        s += dot4(a, x);
    }
    s = warp_reduce(s);
    if ((tid & 31) == 0) red[tid >> 5] = s;
    __syncthreads();
    if (tid < 8) {
        float v = red[tid];
        #pragma unroll
        for (int o = 4; o > 0; o >>= 1) v += __shfl_xor_sync(0xFFu, v, o);
        if (tid == 0) g_sc[l] = v + attn_b[l];
    }
}

// ---------------------------------------------------------------------------
// K1b: softmax (redundant per CTA, 20 values) + context + concat vector.
// ---------------------------------------------------------------------------
__global__ void k1b_ctx(const int* __restrict__ input_ids,
                        const float* __restrict__ enc,
                        const float* __restrict__ emb,
                        float* __restrict__ out)
{
    __shared__ float sw[L];
    const int tid = threadIdx.x;

    if (tid == 0) {
        float m = g_sc[0];
        #pragma unroll
        for (int l = 1; l < L; l++) m = fmaxf(m, g_sc[l]);
        float s = 0.f;
        float e[L];
        #pragma unroll
        for (int l = 0; l < L; l++) { e[l] = __expf(g_sc[l] - m); s += e[l]; }
        float inv = 1.f / s;
        #pragma unroll
        for (int l = 0; l < L; l++) sw[l] = e[l] * inv;
    }
    __syncthreads();

    const int j = blockIdx.x * 128 + tid;
    float ctx = 0.f;
    #pragma unroll
    for (int l = 0; l < L; l++)
        ctx += sw[l] * enc[l * H + j];

    const int id = input_ids[0];
    g_concat[j]     = emb[(long long)id * H + j];
    g_concat[H + j] = ctx;

    if (blockIdx.x == 0 && tid < L) out[V + H + tid] = sw[tid];
}

// ---------------------------------------------------------------------------
// K2: fused comb GEMV (CTAs 0..255: rows of comb_w, len 4096, relu -> g_x)
//     and gh GEMV (CTAs 256..1023: rows of w_hh, len 2048 -> g_gh).
// ---------------------------------------------------------------------------
__global__ void __launch_bounds__(256) k2_comb_gh(
    const float* __restrict__ comb_w, const float* __restrict__ comb_b,
    const float* __restrict__ w_hh,   const float* __restrict__ b_hh,
    const float* __restrict__ hidden)
{
    __shared__ float4 xs[1024];
    const int tid  = threadIdx.x;
    const int warp = tid >> 5;
    const int lane = tid & 31;

    if (blockIdx.x < 256) {
        for (int i = tid; i < 1024; i += 256)
            xs[i] = reinterpret_cast<const float4*>(g_concat)[i];
        __syncthreads();

        const int r = blockIdx.x * 8 + warp;
        const float4* w = reinterpret_cast<const float4*>(comb_w + (long long)r * (2 * H));
        float s = 0.f;
        #pragma unroll 8
        for (int i = lane; i < 1024; i += 32)
            s += dot4(__ldcs(w + i), xs[i]);
        s = warp_reduce(s);
        if (lane == 0) g_x[r] = fmaxf(s + comb_b[r], 0.f);
    } else {
        for (int i = tid; i < 512; i += 256)
            xs[i] = reinterpret_cast<const float4*>(hidden)[i];
        __syncthreads();

        const int r = (blockIdx.x - 256) * 8 + warp;      // 0..6143
        const float4* w = reinterpret_cast<const float4*>(w_hh + (long long)r * H);
        float s = 0.f;
        #pragma unroll 8
        for (int i = lane; i < 512; i += 32)
            s += dot4(__ldcs(w + i), xs[i]);
        s = warp_reduce(s);
        if (lane == 0) g_gh[r] = s + b_hh[r];
    }
}

// ---------------------------------------------------------------------------
// K3: 768 threads (24 warps) per CTA; warp w handles (k_local = w/3,
// gate = w%3): one contiguous 8KB row of w_ih. 3 warps meet per k in shared,
// 8 threads do GRU gate math. grid = 256 -> 6144 streaming warps.
// ---------------------------------------------------------------------------
__global__ void __launch_bounds__(768) k3_gru(
    const float* __restrict__ w_ih, const float* __restrict__ b_ih,
    const float* __restrict__ hidden, float* __restrict__ out)
{
    __shared__ float4 xs[512];
    __shared__ float s_gi[8][3];
    const int tid  = threadIdx.x;
    const int warp = tid >> 5;
    const int lane = tid & 31;

    for (int i = tid; i < 512; i += 768)
        xs[i] = reinterpret_cast<const float4*>(g_x)[i];
    __syncthreads();

    const int k_local = warp / 3;           // 0..7
    const int gate    = warp - k_local * 3; // 0..2
    const int k       = blockIdx.x * 8 + k_local;
    const int row     = k + gate * H;

    const float4* w = reinterpret_cast<const float4*>(w_ih) + (long long)row * 512;
    float s = 0.f;
    #pragma unroll 8
    for (int i = lane; i < 512; i += 32)
        s += dot4(__ldcs(w + i), xs[i]);
    s = warp_reduce(s);
    if (lane == 0) s_gi[k_local][gate] = s + b_ih[row];
    __syncthreads();

    if (tid < 8) {
        const int kk = blockIdx.x * 8 + tid;
        float i_r = s_gi[tid][0], i_z = s_gi[tid][1], i_n = s_gi[tid][2];
        float h_r = g_gh[kk], h_z = g_gh[kk + H], h_n = g_gh[kk + 2 * H];
        float rr = 1.f / (1.f + __expf(-(i_r + h_r)));
        float zz = 1.f / (1.f + __expf(-(i_z + h_z)));
        float nn = tanhf(i_n + rr * h_n);
        float h0 = hidden[kk];
        float hn = (1.f - zz) * nn + zz * h0;
        g_hnew[kk]  = hn;
        out[V + kk] = hn;
    }
}

// ---------------------------------------------------------------------------
// K4: logits = out_w @ h_new + out_b. x staged in shared, streaming weight
// loads, 2 rows per warp. grid = ceil(V/16), block = 256.
// ---------------------------------------------------------------------------
__global__ void __launch_bounds__(256) k4_logits(
    const float* __restrict__ out_w, const float* __restrict__ out_b,
    float* __restrict__ out)
{
    __shared__ float4 xs[512];
    const int tid  = threadIdx.x;
    const int warp = tid >> 5;
    const int lane = tid & 31;

    for (int i = tid; i < 512; i += 256)
        xs[i] = reinterpret_cast<const float4*>(g_hnew)[i];
    __syncthreads();

    const long long r0 = ((long long)blockIdx.x * 8 + warp) * 2;
    if (r0 >= V) return;
    const bool two = (r0 + 1 < V);

    const float4* w0 = reinterpret_cast<const float4*>(out_w) + r0 * 512;
    const float4* w1 = w0 + (two ? 512 : 0);

    float s0 = 0.f, s1 = 0.f;
    #pragma unroll 8
    for (int i = lane; i < 512; i += 32) {
        float4 b = xs[i];
        s0 += dot4(__ldcs(w0 + i), b);
        s1 += dot4(__ldcs(w1 + i), b);
    }
    s0 = warp_reduce(s0);
    s1 = warp_reduce(s1);
    if (lane == 0) {
        out[r0] = s0 + out_b[r0];
        if (two) out[r0 + 1] = s1 + out_b[r0 + 1];
    }
}

// ---------------------------------------------------------------------------
extern "C" void kernel_launch(void* const* d_in, const int* in_sizes, int n_in,
                              void* d_out, int out_size)
{
    const int*   input_ids = (const int*)  d_in[0];
    const float* hidden    = (const float*)d_in[1];
    const float* enc       = (const float*)d_in[2];
    const float* emb       = (const float*)d_in[3];
    const float* attn_w    = (const float*)d_in[4];
    const float* attn_b    = (const float*)d_in[5];
    const float* comb_w    = (const float*)d_in[6];
    const float* comb_b    = (const float*)d_in[7];
    const float* w_ih      = (const float*)d_in[8];
    const float* w_hh      = (const float*)d_in[9];
    const float* b_ih      = (const float*)d_in[10];
    const float* b_hh      = (const float*)d_in[11];
    const float* out_w     = (const float*)d_in[12];
    const float* out_b     = (const float*)d_in[13];
    float* out = (float*)d_out;

    k1a_scores<<<L, 256>>>(input_ids, hidden, emb, attn_w, attn_b);
    k1b_ctx<<<16, 128>>>(input_ids, enc, emb, out);
    k2_comb_gh<<<1024, 256>>>(comb_w, comb_b, w_hh, b_hh, hidden);
    k3_gru<<<H / 8, 768>>>(w_ih, b_ih, hidden, out);
    k4_logits<<<(V + 15) / 16, 256>>>(out_w, out_b, out);
}